// round 12
// baseline (speedup 1.0000x reference)
#include <cuda_runtime.h>
#include <math.h>

#define TT 2048
#define DD 1024
#define BB 4
#define HH 8
#define LL 16
#define CC (TT/LL)     // 128 chunks -> 512 blocks
#define CLL 16
#define CCC (TT/CLL)   // 128 coarse chunks (== fine chunks)
#define RS 256         // float4 per row
#define EPSF 1e-7f

// scratch: coarse per-chunk sums + exclusive prefix (2 MB each, L2-resident)
__device__ float4 g_S[BB*CCC*RS];
__device__ float4 g_E[BB*CCC*RS];

// ---------------- Kernel A: 16-row chunk sums ----------------
__global__ void chunk_sum_kernel(const float4* __restrict__ X) {
    int t = blockIdx.x * blockDim.x + threadIdx.x;   // over B*CCC*RS = 131072
    int d4 = t & (RS - 1);
    int cx = (t >> 8) & (CCC - 1);
    int b  = t >> 15;
    const float4* xp = X + (size_t)(b * TT + cx * CLL) * RS + d4;
    float4 s = make_float4(0.f, 0.f, 0.f, 0.f);
    #pragma unroll 16
    for (int r = 0; r < CLL; r++) {
        float4 v = xp[(size_t)r * RS];
        s.x += v.x; s.y += v.y; s.z += v.z; s.w += v.w;
    }
    g_S[t] = s;
}

// ---------------- Kernel B: exclusive prefix over chunks ----------------
__global__ void chunk_scan_kernel() {
    int t = blockIdx.x * blockDim.x + threadIdx.x;   // over BB*RS = 1024
    int d4 = t & (RS - 1);
    int b  = t >> 8;
    float4 run = make_float4(0.f, 0.f, 0.f, 0.f);
    #pragma unroll 4
    for (int cx = 0; cx < CCC; cx++) {
        int off = (b * CCC + cx) * RS + d4;
        g_E[off] = run;
        float4 v = g_S[off];
        run.x += v.x; run.y += v.y; run.z += v.z; run.w += v.w;
    }
}

// ---------------- Kernel C: main fused kernel ----------------
// grid (128,4)=512 blocks, 512 threads; sub-block q=tid>>8 owns row i+q of each pair
__global__ __launch_bounds__(512, 2)
void attn_kernel(const float* __restrict__ Xf, const float* __restrict__ W,
                 float* __restrict__ out)
{
    const int c = blockIdx.x, b = blockIdx.y;
    const int tid  = threadIdx.x;
    const int q    = tid >> 8;          // sub-block (row parity)
    const int st   = tid & 255;         // sub-thread: owns d = 4*st..4*st+3
    const int lane = tid & 31;
    const int w8i  = (tid >> 5) & 7;    // warp index within sub-block
    const int i0 = c * LL;
    const unsigned FULL = 0xffffffffu;

    __shared__ float2 s_ab[LL + 1][HH];
    __shared__ float  s_red[2][8][8];     // [sub-block][warp][head]
    __shared__ float  s_winv[2][8][12];
    __shared__ float4 s_buf[2][RS * 9];   // 72 KB interleaved staging

    // softmax coefficients
    if (tid < (LL + 1) * HH) {
        int ii = tid >> 3, h = tid & 7;
        int i = i0 + ii;
        float wp = W[h * HH + h];
        float wm = W[(h + 1) * HH + h];
        float ep = expf(wp), em = expf(wm);
        float diff = ep - em;
        float n = (i >= TT) ? (float)TT : (float)(i + 1);
        float Z = n * em + ((i >= h) ? diff : 0.f);
        float Zi = 1.f / Z;
        s_ab[ii][h] = make_float2(em * Zi, (i >= h) ? diff * Zi : 0.f);
    }

    const float4* Xr = reinterpret_cast<const float4*>(Xf) + (size_t)b * TT * RS;

    // exclusive prefix (no top-up: CLL == LL)
    float4 P = g_E[(size_t)(b * CCC + c) * RS + st];

    // rolling window: w[j] = row (i-1-j), i = current pair's first row
    float4 w[7];
    #pragma unroll
    for (int j = 0; j < 7; j++) {
        int r = i0 - 1 - j;
        w[j] = (r >= 0) ? Xr[(size_t)r * RS + st] : make_float4(0.f,0.f,0.f,0.f);
    }
    float4 x0 = Xr[(size_t)i0 * RS + st];
    float4 x1 = Xr[(size_t)(i0 + 1) * RS + st];

    __syncthreads();   // s_ab ready

    auto reduce8 = [&](const float* pp) -> float {
        bool c16 = (lane & 16);
        float qv[4];
        #pragma unroll
        for (int j = 0; j < 4; j++) {
            float keep = c16 ? pp[j+4] : pp[j];
            float send = c16 ? pp[j]   : pp[j+4];
            qv[j] = keep + __shfl_xor_sync(FULL, send, 16);
        }
        bool c8 = (lane & 8);
        float r2[2];
        #pragma unroll
        for (int j = 0; j < 2; j++) {
            float keep = c8 ? qv[j+2] : qv[j];
            float send = c8 ? qv[j]   : qv[j+2];
            r2[j] = keep + __shfl_xor_sync(FULL, send, 8);
        }
        bool c4 = (lane & 4);
        float keep = c4 ? r2[1] : r2[0];
        float send = c4 ? r2[0] : r2[1];
        float s = keep + __shfl_xor_sync(FULL, send, 4);
        s += __shfl_xor_sync(FULL, s, 2);
        s += __shfl_xor_sync(FULL, s, 1);
        return s;
    };

    float* outf = out + (size_t)b * (TT + 1) * DD * (HH + 1);
    const int hh0 = (4 * st) % 9;

    // stage one row into s_buf[q]; SEL(h) must be compile-time per h
    #define STAGE_BODY(II, PQ, SEL)                                          \
    {                                                                        \
        float Pa[4] = {(PQ).x, (PQ).y, (PQ).z, (PQ).w};                      \
        float p[8] = {0,0,0,0,0,0,0,0};                                      \
        _Pragma("unroll")                                                    \
        for (int r = 0; r < 9; r++) {                                        \
            float o[4];                                                      \
            _Pragma("unroll")                                                \
            for (int e = 0; e < 4; e++) {                                    \
                const int idx = 4*r + e;                                     \
                const int dl = idx / 9;                                      \
                const int h  = idx % 9;                                      \
                float val;                                                   \
                if (h == 8) {                                                \
                    float4 xz = SEL(0);                                      \
                    val = (dl==0? xz.x : dl==1? xz.y : dl==2? xz.z : xz.w);  \
                } else {                                                     \
                    float2 ab = s_ab[II][h];                                 \
                    float4 xs = SEL(h);                                      \
                    float xh = (dl==0? xs.x : dl==1? xs.y : dl==2? xs.z : xs.w); \
                    val = fmaf(ab.y, xh, ab.x * Pa[dl]);                     \
                    p[h] += val * val;                                       \
                }                                                            \
                o[e] = val;                                                  \
            }                                                                \
            s_buf[q][st * 9 + r] = make_float4(o[0], o[1], o[2], o[3]);      \
        }                                                                    \
        float s = reduce8(p);                                                \
        if ((lane & 3) == 0) s_red[q][w8i][lane >> 2] = s;                   \
    }

    auto copy_row = [&](int i) {
        if (lane < 12) {
            int h = (lane < 9) ? lane : lane - 9;
            float val = 1.0f;
            if (h < 8) {
                float ssum = 0.f;
                #pragma unroll
                for (int wq = 0; wq < 8; wq++) ssum += s_red[q][wq][h];
                val = 1.f / (sqrtf(ssum) + EPSF);
            }
            s_winv[q][w8i][lane] = val;
        }
        __syncwarp();
        float4* rowp = reinterpret_cast<float4*>(outf + (size_t)i * DD * (HH + 1));
        int hh = hh0;
        #pragma unroll
        for (int j = 0; j < 9; j++) {
            float4 v = s_buf[q][j * 256 + st];
            float4 o = make_float4(v.x * s_winv[q][w8i][hh],
                                   v.y * s_winv[q][w8i][hh + 1],
                                   v.z * s_winv[q][w8i][hh + 2],
                                   v.w * s_winv[q][w8i][hh + 3]);
            rowp[j * 256 + st] = o;
            hh += 7; if (hh >= 9) hh -= 9;   // 1024 mod 9 == 7
        }
    };

    #pragma unroll 1
    for (int pr = 0; pr < LL / 2; pr++) {
        const int ii = 2 * pr;
        const int i  = i0 + ii;

        if (q == 0) {
            float4 Pq = make_float4(P.x + x0.x, P.y + x0.y, P.z + x0.z, P.w + x0.w);
            // row i: h==0 -> x0, h>=1 -> w[h-1]
            #define SEL_A(h) ((h) == 0 ? x0 : w[(h)-1])
            STAGE_BODY(ii, Pq, SEL_A)
            #undef SEL_A
        } else {
            float4 Pq = make_float4(P.x + x0.x + x1.x, P.y + x0.y + x1.y,
                                    P.z + x0.z + x1.z, P.w + x0.w + x1.w);
            // row i+1: h==0 -> x1, h==1 -> x0, h>=2 -> w[h-2]
            #define SEL_B(h) ((h) == 0 ? x1 : (h) == 1 ? x0 : w[(h)-2])
            STAGE_BODY(ii + 1, Pq, SEL_B)
            #undef SEL_B
        }

        // advance P and window (registers; before BAR is fine)
        P.x += x0.x + x1.x; P.y += x0.y + x1.y;
        P.z += x0.z + x1.z; P.w += x0.w + x1.w;
        #pragma unroll
        for (int j = 6; j >= 2; j--) w[j] = w[j-2];
        w[1] = x0; w[0] = x1;

        // prefetch next pair (clamped)
        int rn0 = i + 2; if (rn0 > TT - 1) rn0 = TT - 1;
        int rn1 = i + 3; if (rn1 > TT - 1) rn1 = TT - 1;
        float4 xn0 = Xr[(size_t)rn0 * RS + st];
        float4 xn1 = Xr[(size_t)rn1 * RS + st];

        __syncthreads();          // BAR1: both rows staged
        copy_row(i + q);
        __syncthreads();          // BAR2: s_buf free for next pair

        x0 = xn0; x1 = xn1;
    }

    // epilogue: row i = T (last chunk only). X_t row T zero; P_T excludes row 0.
    if (c == CC - 1) {
        if (q == 0) {
            float4 x0r = Xr[st];
            float4 Pq = make_float4(P.x - x0r.x, P.y - x0r.y, P.z - x0r.z, P.w - x0r.w);
            float4 zz = make_float4(0.f, 0.f, 0.f, 0.f);
            // row T: h==0 -> zero row; h>=1 -> w[h-1] = row T-h
            #define SEL_E(h) ((h) == 0 ? zz : w[(h)-1])
            STAGE_BODY(LL, Pq, SEL_E)
            #undef SEL_E
        }
        __syncthreads();
        if (q == 0) copy_row(TT);
    }
}

extern "C" void kernel_launch(void* const* d_in, const int* in_sizes, int n_in,
                              void* d_out, int out_size) {
    const float* X = (const float*)d_in[0];
    const float* W = (const float*)d_in[1];
    float* out = (float*)d_out;
    (void)in_sizes; (void)n_in; (void)out_size;

    chunk_sum_kernel<<<(BB * CCC * RS) / 256, 256>>>((const float4*)X);
    chunk_scan_kernel<<<(BB * RS) / 256, 256>>>();
    dim3 grid(CC, BB);
    attn_kernel<<<grid, 512>>>(X, W, out);
}

// round 13
// speedup vs baseline: 1.3884x; 1.3884x over previous
#include <cuda_runtime.h>
#include <math.h>

#define TT 2048
#define DD 1024
#define BB 4
#define HH 8
#define LL 16
#define CC (TT/LL)     // 128 chunks -> 512 blocks
#define CLL 16
#define CCC (TT/CLL)   // 128 coarse chunks (== fine chunks)
#define RS 256         // float4 per row
#define EPSF 1e-7f

// scratch: per-chunk sums + exclusive prefix (2 MB each, L2-resident)
__device__ float4 g_S[BB*CCC*RS];
__device__ float4 g_E[BB*CCC*RS];

// ---------------- Kernel A: 16-row chunk sums ----------------
__global__ void chunk_sum_kernel(const float4* __restrict__ X) {
    int t = blockIdx.x * blockDim.x + threadIdx.x;   // over B*CCC*RS = 131072
    int d4 = t & (RS - 1);
    int cx = (t >> 8) & (CCC - 1);
    int b  = t >> 15;
    const float4* xp = X + (size_t)(b * TT + cx * CLL) * RS + d4;
    float4 s = make_float4(0.f, 0.f, 0.f, 0.f);
    #pragma unroll 16
    for (int r = 0; r < CLL; r++) {
        float4 v = xp[(size_t)r * RS];
        s.x += v.x; s.y += v.y; s.z += v.z; s.w += v.w;
    }
    g_S[t] = s;
}

// ---------------- Kernel B: exclusive prefix over chunks ----------------
__global__ void chunk_scan_kernel() {
    int t = blockIdx.x * blockDim.x + threadIdx.x;   // over BB*RS = 1024
    int d4 = t & (RS - 1);
    int b  = t >> 8;
    float4 run = make_float4(0.f, 0.f, 0.f, 0.f);
    #pragma unroll 8
    for (int cx = 0; cx < CCC; cx++) {
        int off = (b * CCC + cx) * RS + d4;
        g_E[off] = run;
        float4 v = g_S[off];
        run.x += v.x; run.y += v.y; run.z += v.z; run.w += v.w;
    }
}

// ---------------- Kernel C: main fused kernel (R5 structure, LL=16) ----------------
// grid: (128, 4) = 512 blocks, 256 threads, 3 CTAs/SM
__global__ __launch_bounds__(256, 3)
void attn_kernel(const float* __restrict__ Xf, const float* __restrict__ W,
                 float* __restrict__ out)
{
    const int c = blockIdx.x, b = blockIdx.y;
    const int tid  = threadIdx.x;
    const int lane = tid & 31, warp = tid >> 5;
    const int i0 = c * LL;
    const unsigned FULL = 0xffffffffu;

    __shared__ float2 s_ab[LL + 1][HH];
    __shared__ float  s_red[2][8][8];     // [parity][warp][head]
    __shared__ float  s_winv[8][12];      // per-warp inv norms, wrap-extended
    __shared__ float4 s_buf[2][RS * 9];   // 72 KB interleaved staging (raw)

    // softmax coefficients ((LL+1)*HH = 136 < 256)
    if (tid < (LL + 1) * HH) {
        int ii = tid >> 3, h = tid & 7;
        int i = i0 + ii;
        float wp = W[h * HH + h];
        float wm = W[(h + 1) * HH + h];
        float ep = expf(wp), em = expf(wm);
        float diff = ep - em;
        float n = (i >= TT) ? (float)TT : (float)(i + 1);
        float Z = n * em + ((i >= h) ? diff : 0.f);
        float Zi = 1.f / Z;
        s_ab[ii][h] = make_float2(em * Zi, (i >= h) ? diff * Zi : 0.f);
    }

    const float4* Xr = reinterpret_cast<const float4*>(Xf) + (size_t)b * TT * RS;

    // exclusive prefix: single scanned entry, no top-up (CLL == LL)
    float4 P = g_E[(size_t)(b * CCC + c) * RS + tid];

    // rolling window: w[j] = row (i-1-j)
    float4 w[7];
    #pragma unroll
    for (int j = 0; j < 7; j++) {
        int r = i0 - 1 - j;
        w[j] = (r >= 0) ? Xr[(size_t)r * RS + tid] : make_float4(0.f,0.f,0.f,0.f);
    }
    float4 x = Xr[(size_t)i0 * RS + tid];

    __syncthreads();   // s_ab ready

    auto reduce8 = [&](const float* pp) -> float {
        bool b16 = (lane & 16);
        float q[4];
        #pragma unroll
        for (int j = 0; j < 4; j++) {
            float keep = b16 ? pp[j+4] : pp[j];
            float send = b16 ? pp[j]   : pp[j+4];
            q[j] = keep + __shfl_xor_sync(FULL, send, 16);
        }
        bool b8 = (lane & 8);
        float r2[2];
        #pragma unroll
        for (int j = 0; j < 2; j++) {
            float keep = b8 ? q[j+2] : q[j];
            float send = b8 ? q[j]   : q[j+2];
            r2[j] = keep + __shfl_xor_sync(FULL, send, 8);
        }
        bool b4 = (lane & 4);
        float keep = b4 ? r2[1] : r2[0];
        float send = b4 ? r2[0] : r2[1];
        float s = keep + __shfl_xor_sync(FULL, send, 4);
        s += __shfl_xor_sync(FULL, s, 2);
        s += __shfl_xor_sync(FULL, s, 1);
        return s;
    };

    float* outf = out + (size_t)b * (TT + 1) * DD * (HH + 1);
    const int hh0 = (4 * tid) % 9;

    // stage raw interleaved values + norm partials (pre-barrier work)
    auto stage_row = [&](int par, int ii, float4 xv) {
        float Pa[4] = {P.x, P.y, P.z, P.w};
        float Xa[4] = {xv.x, xv.y, xv.z, xv.w};
        float p[8] = {0,0,0,0,0,0,0,0};
        #pragma unroll
        for (int r = 0; r < 9; r++) {
            float o[4];
            #pragma unroll
            for (int e = 0; e < 4; e++) {
                const int idx = 4*r + e;
                const int dl = idx / 9;         // compile-time
                const int h  = idx % 9;         // compile-time
                float val;
                if (h == 8) {
                    val = Xa[dl];
                } else {
                    float2 ab = s_ab[ii][h];
                    float xh = (h == 0) ? Xa[dl]
                             : (dl == 0 ? w[h-1].x : dl == 1 ? w[h-1].y
                                        : dl == 2 ? w[h-1].z : w[h-1].w);
                    val = fmaf(ab.y, xh, ab.x * Pa[dl]);
                    p[h] += val * val;
                }
                o[e] = val;
            }
            s_buf[par][tid * 9 + r] = make_float4(o[0], o[1], o[2], o[3]);
        }
        float s = reduce8(p);
        if ((lane & 3) == 0) s_red[par][warp][lane >> 2] = s;
    };

    // copy-out with on-the-fly normalization (post-barrier work)
    auto copy_row = [&](int par, int i) {
        if (lane < 12) {
            int h = (lane < 9) ? lane : lane - 9;
            float val = 1.0f;
            if (h < 8) {
                float ssum = 0.f;
                #pragma unroll
                for (int w8 = 0; w8 < 8; w8++) ssum += s_red[par][w8][h];
                val = 1.f / (sqrtf(ssum) + EPSF);
            }
            s_winv[warp][lane] = val;
        }
        __syncwarp();
        float4* rowp = reinterpret_cast<float4*>(outf + (size_t)i * DD * (HH + 1));
        int hh = hh0;
        #pragma unroll
        for (int j = 0; j < 9; j++) {
            float4 v = s_buf[par][j * 256 + tid];
            float4 o = make_float4(v.x * s_winv[warp][hh],
                                   v.y * s_winv[warp][hh + 1],
                                   v.z * s_winv[warp][hh + 2],
                                   v.w * s_winv[warp][hh + 3]);
            rowp[j * 256 + tid] = o;
            hh += 7; if (hh >= 9) hh -= 9;   // 1024 mod 9 == 7
        }
    };

    #pragma unroll 1
    for (int ii = 0; ii < LL; ii++) {
        const int i = i0 + ii;
        const int par = ii & 1;
        P.x += x.x; P.y += x.y; P.z += x.z; P.w += x.w;
        stage_row(par, ii, x);
        int rn = i + 1; if (rn > TT - 1) rn = TT - 1;
        float4 xn = Xr[(size_t)rn * RS + tid];   // prefetch under BAR+copy
        __syncthreads();                          // single barrier per row
        copy_row(par, i);
        #pragma unroll
        for (int j = 6; j > 0; j--) w[j] = w[j-1];
        w[0] = x;
        x = xn;
    }

    // epilogue: row i = T (last chunk only). X_t row T is zero; P_T excludes row 0.
    if (c == CC - 1) {
        float4 x0r = Xr[tid];
        P.x -= x0r.x; P.y -= x0r.y; P.z -= x0r.z; P.w -= x0r.w;
        stage_row(0, LL, make_float4(0.f, 0.f, 0.f, 0.f));
        __syncthreads();
        copy_row(0, TT);
    }
}

extern "C" void kernel_launch(void* const* d_in, const int* in_sizes, int n_in,
                              void* d_out, int out_size) {
    const float* X = (const float*)d_in[0];
    const float* W = (const float*)d_in[1];
    float* out = (float*)d_out;
    (void)in_sizes; (void)n_in; (void)out_size;

    chunk_sum_kernel<<<(BB * CCC * RS) / 256, 256>>>((const float4*)X);
    chunk_scan_kernel<<<(BB * RS) / 256, 256>>>();
    dim3 grid(CC, BB);
    attn_kernel<<<grid, 256>>>(X, W, out);
}

// round 15
// speedup vs baseline: 1.4655x; 1.0555x over previous
#include <cuda_runtime.h>
#include <math.h>

#define TT 2048
#define DD 1024
#define BB 4
#define HH 8
#define CLL 16
#define CCC (TT/CLL)   // 128 coarse chunks
#define RS 256         // float4 per row
#define EPSF 1e-7f

#define NBLK 111       // blocks per batch -> grid 444 = 3 CTAs/SM * 148 SMs
#define MAXROWS 19     // max rows per block (51 blocks x19 + 60 x18 = 2049)

// scratch: per-chunk sums + exclusive prefix (2 MB each, L2-resident)
__device__ float4 g_S[BB*CCC*RS];
__device__ float4 g_E[BB*CCC*RS];

// ---------------- Kernel A: 16-row chunk sums ----------------
__global__ void chunk_sum_kernel(const float4* __restrict__ X) {
    int t = blockIdx.x * blockDim.x + threadIdx.x;   // over B*CCC*RS = 131072
    int d4 = t & (RS - 1);
    int cx = (t >> 8) & (CCC - 1);
    int b  = t >> 15;
    const float4* xp = X + (size_t)(b * TT + cx * CLL) * RS + d4;
    float4 s = make_float4(0.f, 0.f, 0.f, 0.f);
    #pragma unroll 16
    for (int r = 0; r < CLL; r++) {
        float4 v = xp[(size_t)r * RS];
        s.x += v.x; s.y += v.y; s.z += v.z; s.w += v.w;
    }
    g_S[t] = s;
}

// ---------------- Kernel B: exclusive prefix over chunks ----------------
__global__ void chunk_scan_kernel() {
    int t = blockIdx.x * blockDim.x + threadIdx.x;   // over BB*RS = 1024
    int d4 = t & (RS - 1);
    int b  = t >> 8;
    float4 run = make_float4(0.f, 0.f, 0.f, 0.f);
    #pragma unroll 8
    for (int cx = 0; cx < CCC; cx++) {
        int off = (b * CCC + cx) * RS + d4;
        g_E[off] = run;
        float4 v = g_S[off];
        run.x += v.x; run.y += v.y; run.z += v.z; run.w += v.w;
    }
}

// ---------------- Kernel C: single-wave persistent-range kernel ----------------
// grid (111, 4) = 444 blocks = exactly 3 CTAs/SM on 148 SMs, 256 threads
__global__ __launch_bounds__(256, 3)
void attn_kernel(const float* __restrict__ Xf, const float* __restrict__ W,
                 float* __restrict__ out)
{
    const int jb = blockIdx.x, b = blockIdx.y;
    const int tid  = threadIdx.x;
    const int lane = tid & 31, warp = tid >> 5;
    const unsigned FULL = 0xffffffffu;

    // contiguous row range [s, e) within [0, 2049): first 51 blocks 19 rows, rest 18
    const int s = jb * 18 + (jb < 51 ? jb : 51);
    const int len = (jb < 51) ? 19 : 18;
    const int e = s + len;

    __shared__ float2 s_ab[MAXROWS][HH];
    __shared__ float  s_red[2][8][8];     // [parity][warp][head]
    __shared__ float  s_winv[8][12];      // per-warp inv norms, wrap-extended
    __shared__ float4 s_buf[2][RS * 9];   // 72 KB interleaved staging (raw)

    // softmax coefficients for rows s..e-1  (len*8 <= 152 < 256)
    if (tid < len * HH) {
        int ii = tid >> 3, h = tid & 7;
        int i = s + ii;
        float wp = W[h * HH + h];
        float wm = W[(h + 1) * HH + h];
        float ep = expf(wp), em = expf(wm);
        float diff = ep - em;
        float n = (i >= TT) ? (float)TT : (float)(i + 1);
        float Z = n * em + ((i >= h) ? diff : 0.f);
        float Zi = 1.f / Z;
        s_ab[ii][h] = make_float2(em * Zi, (i >= h) ? diff * Zi : 0.f);
    }

    const float4* Xr = reinterpret_cast<const float4*>(Xf) + (size_t)b * TT * RS;

    // exclusive prefix at row s: scanned coarse entry + <=15 top-up rows (L2 hits)
    const int cc = s >> 4;   // s / CLL
    float4 P = g_E[(size_t)(b * CCC + cc) * RS + tid];
    for (int r = cc * CLL; r < s; r++) {
        float4 v = Xr[(size_t)r * RS + tid];
        P.x += v.x; P.y += v.y; P.z += v.z; P.w += v.w;
    }

    // rolling window: w[j] = row (s-1-j)
    float4 w[7];
    #pragma unroll
    for (int j = 0; j < 7; j++) {
        int r = s - 1 - j;
        w[j] = (r >= 0) ? Xr[(size_t)r * RS + tid] : make_float4(0.f,0.f,0.f,0.f);
    }
    float4 x = (s < TT) ? Xr[(size_t)s * RS + tid] : make_float4(0.f,0.f,0.f,0.f);

    __syncthreads();   // s_ab ready

    auto reduce8 = [&](const float* pp) -> float {
        bool b16 = (lane & 16);
        float q[4];
        #pragma unroll
        for (int j = 0; j < 4; j++) {
            float keep = b16 ? pp[j+4] : pp[j];
            float send = b16 ? pp[j]   : pp[j+4];
            q[j] = keep + __shfl_xor_sync(FULL, send, 16);
        }
        bool b8 = (lane & 8);
        float r2[2];
        #pragma unroll
        for (int j = 0; j < 2; j++) {
            float keep = b8 ? q[j+2] : q[j];
            float send = b8 ? q[j]   : q[j+2];
            r2[j] = keep + __shfl_xor_sync(FULL, send, 8);
        }
        bool b4 = (lane & 4);
        float keep = b4 ? r2[1] : r2[0];
        float send = b4 ? r2[0] : r2[1];
        float sv = keep + __shfl_xor_sync(FULL, send, 4);
        sv += __shfl_xor_sync(FULL, sv, 2);
        sv += __shfl_xor_sync(FULL, sv, 1);
        return sv;
    };

    float* outf = out + (size_t)b * (TT + 1) * DD * (HH + 1);
    const int hh0 = (4 * tid) % 9;

    // stage raw interleaved values + norm partials (pre-barrier work)
    auto stage_row = [&](int par, int ii, float4 xv) {
        float Pa[4] = {P.x, P.y, P.z, P.w};
        float Xa[4] = {xv.x, xv.y, xv.z, xv.w};
        float p[8] = {0,0,0,0,0,0,0,0};
        #pragma unroll
        for (int r = 0; r < 9; r++) {
            float o[4];
            #pragma unroll
            for (int e2 = 0; e2 < 4; e2++) {
                const int idx = 4*r + e2;
                const int dl = idx / 9;         // compile-time
                const int h  = idx % 9;         // compile-time
                float val;
                if (h == 8) {
                    val = Xa[dl];
                } else {
                    float2 ab = s_ab[ii][h];
                    float xh = (h == 0) ? Xa[dl]
                             : (dl == 0 ? w[h-1].x : dl == 1 ? w[h-1].y
                                        : dl == 2 ? w[h-1].z : w[h-1].w);
                    val = fmaf(ab.y, xh, ab.x * Pa[dl]);
                    p[h] += val * val;
                }
                o[e2] = val;
            }
            s_buf[par][tid * 9 + r] = make_float4(o[0], o[1], o[2], o[3]);
        }
        float sv = reduce8(p);
        if ((lane & 3) == 0) s_red[par][warp][lane >> 2] = sv;
    };

    // copy-out with on-the-fly normalization (post-barrier work)
    auto copy_row = [&](int par, int i) {
        if (lane < 12) {
            int h = (lane < 9) ? lane : lane - 9;
            float val = 1.0f;
            if (h < 8) {
                float ssum = 0.f;
                #pragma unroll
                for (int w8 = 0; w8 < 8; w8++) ssum += s_red[par][w8][h];
                val = 1.f / (sqrtf(ssum) + EPSF);
            }
            s_winv[warp][lane] = val;
        }
        __syncwarp();
        float4* rowp = reinterpret_cast<float4*>(outf + (size_t)i * DD * (HH + 1));
        int hh = hh0;
        #pragma unroll
        for (int j = 0; j < 9; j++) {
            float4 v = s_buf[par][j * 256 + tid];
            float4 o = make_float4(v.x * s_winv[warp][hh],
                                   v.y * s_winv[warp][hh + 1],
                                   v.z * s_winv[warp][hh + 2],
                                   v.w * s_winv[warp][hh + 3]);
            rowp[j * 256 + tid] = o;
            hh += 7; if (hh >= 9) hh -= 9;   // 1024 mod 9 == 7
        }
    };

    #pragma unroll 1
    for (int ii = 0; ii < len; ii++) {
        const int i = s + ii;
        const int par = ii & 1;
        if (i < TT) {
            P.x += x.x; P.y += x.y; P.z += x.z; P.w += x.w;
            stage_row(par, ii, x);
            int rn = i + 1; if (rn > TT - 1) rn = TT - 1;
            float4 xn = Xr[(size_t)rn * RS + tid];   // prefetch under BAR+copy
            __syncthreads();
            copy_row(par, i);
            #pragma unroll
            for (int j = 6; j > 0; j--) w[j] = w[j-1];
            w[0] = x;
            x = xn;
        } else {
            // row i == TT: X_t row is zero; P_T = S_{T-1} - X[row 0]
            float4 x0r = Xr[tid];
            P.x -= x0r.x; P.y -= x0r.y; P.z -= x0r.z; P.w -= x0r.w;
            stage_row(par, ii, make_float4(0.f, 0.f, 0.f, 0.f));
            __syncthreads();
            copy_row(par, TT);
        }
    }
}

extern "C" void kernel_launch(void* const* d_in, const int* in_sizes, int n_in,
                              void* d_out, int out_size) {
    const float* X = (const float*)d_in[0];
    const float* W = (const float*)d_in[1];
    float* out = (float*)d_out;
    (void)in_sizes; (void)n_in; (void)out_size;

    chunk_sum_kernel<<<(BB * CCC * RS) / 256, 256>>>((const float4*)X);
    chunk_scan_kernel<<<(BB * RS) / 256, 256>>>();
    dim3 grid(NBLK, BB);
    attn_kernel<<<grid, 256>>>(X, W, out);
}